// round 5
// baseline (speedup 1.0000x reference)
#include <cuda_runtime.h>
#include <cstdint>

// Reference = patchify ∘ depatchify == identity. The whole problem is a
// 256 MiB device-to-device copy.
//
// R1 (SM float4 copy): 74.0us kernel, HBM 6539 GB/s (81.7% of 8TB/s spec).
// DRAM-bound with SM-side fully idle (issue=3.3%). R2: route the copy
// through the copy engine via cudaMemcpyAsync — a single graph memcpy node,
// no kernel launch, CE request scheduling is turnaround-optimized and
// typically lands closer to the HBM ceiling than SM LDG/STG streams.
//
// Graph-capture-legal: cudaMemcpyAsync D2D is explicitly allowed.

extern "C" void kernel_launch(void* const* d_in, const int* in_sizes, int n_in,
                              void* d_out, int out_size)
{
    const void* src = d_in[0];
    // out_size elements of float32 (64*1*1024*1024 = 67,108,864 floats).
    size_t bytes = (size_t)out_size * sizeof(float);
    cudaMemcpyAsync(d_out, src, bytes, cudaMemcpyDeviceToDevice, 0);
}

// round 6
// speedup vs baseline: 1.0246x; 1.0246x over previous
#include <cuda_runtime.h>
#include <cstdint>

// Reference = patchify ∘ depatchify == identity -> 256 MiB D2D copy.
//
// R1: SM float4 copy, kernel 74.0us, HBM 6539 GB/s (82% spec), dur 82.1us.
// R2: CE memcpy regressed (84.0us) — SM path already at the path-independent
//     LTS/DRAM ceiling; CE is no better on B300.
// R3: same SM copy with (a) streaming cache hints (.cs) on both load and
//     store — zero-reuse stream, evict-first reduces L2 churn / write-allocate
//     pressure; (b) 8 float4 per thread (MLP=8) for deeper DRAM queues and
//     better turnaround scheduling.
//
// 16,777,216 float4 total. 8 per thread -> 2,097,152 threads
// -> 8192 blocks x 256 threads, exact cover.
// Block b covers float4 [b*2048, (b+1)*2048); thread t touches
// t + k*256, k=0..7 (each access fully coalesced, 128B lines).

__global__ __launch_bounds__(256) void identity_copy_kernel(
    const float4* __restrict__ src, float4* __restrict__ dst)
{
    size_t base = (size_t)blockIdx.x * 2048 + threadIdx.x;

    // Front-batch all 8 loads (MLP=8), then all stores.
    float4 v0 = __ldcs(&src[base + 0 * 256]);
    float4 v1 = __ldcs(&src[base + 1 * 256]);
    float4 v2 = __ldcs(&src[base + 2 * 256]);
    float4 v3 = __ldcs(&src[base + 3 * 256]);
    float4 v4 = __ldcs(&src[base + 4 * 256]);
    float4 v5 = __ldcs(&src[base + 5 * 256]);
    float4 v6 = __ldcs(&src[base + 6 * 256]);
    float4 v7 = __ldcs(&src[base + 7 * 256]);

    __stcs(&dst[base + 0 * 256], v0);
    __stcs(&dst[base + 1 * 256], v1);
    __stcs(&dst[base + 2 * 256], v2);
    __stcs(&dst[base + 3 * 256], v3);
    __stcs(&dst[base + 4 * 256], v4);
    __stcs(&dst[base + 5 * 256], v5);
    __stcs(&dst[base + 6 * 256], v6);
    __stcs(&dst[base + 7 * 256], v7);
}

extern "C" void kernel_launch(void* const* d_in, const int* in_sizes, int n_in,
                              void* d_out, int out_size)
{
    const float4* src = (const float4*)d_in[0];
    float4* dst = (float4*)d_out;

    // 16,777,216 float4 / 8 per thread / 256 threads = 8192 blocks.
    identity_copy_kernel<<<8192, 256>>>(src, dst);
}

// round 8
// speedup vs baseline: 1.0250x; 1.0004x over previous
#include <cuda_runtime.h>
#include <cstdint>

// Reference = patchify ∘ depatchify == identity -> 256 MiB D2D copy.
//
// History:
//  R1: 4xfloat4/thread, 16384 blocks, plain ld/st. kernel 74.0us, occ 79%,
//      DRAM 82.5%, HBM 6539 GB/s. Best.
//  R2: CE memcpy — 84.0us, regression (SM path already at path-indep ceiling).
//  R3: 8xfloat4 + .cs — kernel 75.6us: regs 40 -> occ 61% -> DRAM 80.5%.
//      MLP-per-thread gain < chip-wide concurrency loss. Confounded .cs test.
//  R4: R1 geometry (24 regs, occ ~79%) with .cs hints ONLY — unconfounded
//      test of evict-first streaming policy on the known-best geometry.
//
// 16,777,216 float4; 4 per thread -> 4,194,304 threads -> 16384 blocks x 256.
// Block b covers float4 [b*1024, (b+1)*1024); thread t touches t + k*256.

__global__ __launch_bounds__(256) void identity_copy_kernel(
    const float4* __restrict__ src, float4* __restrict__ dst)
{
    size_t base = (size_t)blockIdx.x * 1024 + threadIdx.x;

    // Front-batch loads (MLP=4), streaming (evict-first) policy both ways.
    float4 v0 = __ldcs(&src[base + 0 * 256]);
    float4 v1 = __ldcs(&src[base + 1 * 256]);
    float4 v2 = __ldcs(&src[base + 2 * 256]);
    float4 v3 = __ldcs(&src[base + 3 * 256]);

    __stcs(&dst[base + 0 * 256], v0);
    __stcs(&dst[base + 1 * 256], v1);
    __stcs(&dst[base + 2 * 256], v2);
    __stcs(&dst[base + 3 * 256], v3);
}

extern "C" void kernel_launch(void* const* d_in, const int* in_sizes, int n_in,
                              void* d_out, int out_size)
{
    const float4* src = (const float4*)d_in[0];
    float4* dst = (float4*)d_out;

    identity_copy_kernel<<<16384, 256>>>(src, dst);
}

// round 10
// speedup vs baseline: 1.0282x; 1.0031x over previous
#include <cuda_runtime.h>
#include <cstdint>

// Reference = patchify ∘ depatchify == identity -> 256 MiB D2D copy.
//
// History:
//  R1: 4xfloat4/thread, 16384 blks, plain ld/st. kernel 74.0us, DRAM 82.5%. Best.
//  R2: CE memcpy — 84.0us regression (SM path already at path-indep LTS cap).
//  R3: 8xfloat4 + .cs — 75.6us: regs 40 -> occ 61% -> DRAM 80.5%. Worse.
//  R4: 4xfloat4 + .cs — 74.7us, DRAM 81.3%. .cs is NEUTRAL behind the LTS cap.
//  R5: geometry probe in the opposite direction: 2xfloat4/thread, 32768
//      blocks. Same chip-wide outstanding-request product, more independent
//      warp streams, fewer regs (~16) -> ~100% occ. Expect neutral to -1us;
//      if neutral, 74us is the HW copy ceiling and we're done.
//
// 16,777,216 float4; 2 per thread -> 8,388,608 threads -> 32768 blocks x 256.
// Block b covers float4 [b*512, (b+1)*512); thread t touches t, t+256.

__global__ __launch_bounds__(256) void identity_copy_kernel(
    const float4* __restrict__ src, float4* __restrict__ dst)
{
    size_t base = (size_t)blockIdx.x * 512 + threadIdx.x;

    float4 v0 = src[base];
    float4 v1 = src[base + 256];

    dst[base]       = v0;
    dst[base + 256] = v1;
}

extern "C" void kernel_launch(void* const* d_in, const int* in_sizes, int n_in,
                              void* d_out, int out_size)
{
    const float4* src = (const float4*)d_in[0];
    float4* dst = (float4*)d_out;

    identity_copy_kernel<<<32768, 256>>>(src, dst);
}